// round 15
// baseline (speedup 1.0000x reference)
#include <cuda_runtime.h>
#include <cstdint>
#include <mma.h>
#include <cuda_bf16.h>

using namespace nvcuda;

// Problem constants (fixed shapes)
#define MB 32      // effective batch m = B*T (raw-reinterpret reshape)
#define CC 256     // channels
#define NN 1024    // pixels per map (32*32)
#define RR 320     // fused qkv rows: 32 q + 32 k + 256 v

typedef unsigned long long u64;

// Scratch (module-load allocated; no cudaMalloc anywhere)
__device__ float g_qkv[MB * RR * NN];                         // 40 MB fp32 q,k,v
__device__ __nv_bfloat16 g_attn_bf[(size_t)MB * NN * NN];     // 67 MB exp(E) bf16
__device__ __nv_bfloat16 g_vb[(size_t)MB * CC * NN];          // 17 MB V*(1/Z) bf16
__device__ __nv_bfloat16 g_xb[(size_t)MB * CC * NN];          // 17 MB x in bf16
__device__ __nv_bfloat16 g_wvb[CC * CC];                      // wv in bf16

// ---- orchestration objects (static-init; no device-memory allocation) ------
static cudaStream_t g_s2;
static cudaEvent_t g_e0, g_eqk, g_ecvt, g_eA0, g_eend;
namespace {
struct OrchInit {
    OrchInit() {
        cudaStreamCreateWithFlags(&g_s2, cudaStreamNonBlocking);
        cudaEventCreateWithFlags(&g_e0,   cudaEventDisableTiming);
        cudaEventCreateWithFlags(&g_eqk,  cudaEventDisableTiming);
        cudaEventCreateWithFlags(&g_ecvt, cudaEventDisableTiming);
        cudaEventCreateWithFlags(&g_eA0,  cudaEventDisableTiming);
        cudaEventCreateWithFlags(&g_eend, cudaEventDisableTiming);
    }
};
static OrchInit g_orch_init;
}

// ---- cp.async helpers (arch-neutral, sm_80+) --------------------------------
__device__ __forceinline__ uint32_t smem_u32(const void* p) {
    uint32_t a;
    asm("{ .reg .u64 t; cvta.to.shared.u64 t, %1; cvt.u32.u64 %0, t; }"
        : "=r"(a) : "l"(p));
    return a;
}
__device__ __forceinline__ void cp16(uint32_t dst, const void* src) {
    asm volatile("cp.async.cg.shared.global [%0], [%1], 16;"
                 :: "r"(dst), "l"(src));
}
#define CP_COMMIT() asm volatile("cp.async.commit_group;" ::: "memory")
#define CP_WAIT(n)  asm volatile("cp.async.wait_group %0;" :: "n"(n) : "memory")

// ---------------------------------------------------------------------------
// Kernel 0: convert x and wv to bf16 (one-time, ~50MB traffic)
// ---------------------------------------------------------------------------
#define XB4 (MB * CC * NN / 4)
#define WV4 (CC * CC / 4)
__global__ __launch_bounds__(256) void k_cvt(
    const float* __restrict__ x, const float* __restrict__ wv)
{
    int idx = blockIdx.x * 256 + threadIdx.x;
    if (idx < XB4) {
        float4 v = ((const float4*)x)[idx];
        __nv_bfloat162 h0 = __floats2bfloat162_rn(v.x, v.y);
        __nv_bfloat162 h1 = __floats2bfloat162_rn(v.z, v.w);
        uint2 st;
        st.x = *(uint32_t*)&h0; st.y = *(uint32_t*)&h1;
        ((uint2*)g_xb)[idx] = st;
    } else if (idx < XB4 + WV4) {
        int k = idx - XB4;
        float4 v = ((const float4*)wv)[k];
        __nv_bfloat162 h0 = __floats2bfloat162_rn(v.x, v.y);
        __nv_bfloat162 h1 = __floats2bfloat162_rn(v.z, v.w);
        uint2 st;
        st.x = *(uint32_t*)&h0; st.y = *(uint32_t*)&h1;
        ((uint2*)g_wvb)[k] = st;
    }
}

// ---------------------------------------------------------------------------
// Kernel 1a: q,k projection via tf32 wmma (64 rows only).
// ---------------------------------------------------------------------------
#define K1_A_LD 40
#define K1_B_LD 136
#define K1_A_BYTES (64 * K1_A_LD * 4)
#define K1_B_BYTES (32 * K1_B_LD * 4)
#define K1_STAGE (K1_A_BYTES + K1_B_BYTES)
#define K1_SCR_LD 36
#define SMEM_K1 (2 * K1_STAGE)

__global__ __launch_bounds__(256) void k_qkv_qk(
    const float* __restrict__ x,
    const float* __restrict__ wq, const float* __restrict__ bq,
    const float* __restrict__ wk, const float* __restrict__ bk)
{
    extern __shared__ __align__(16) char smc[];
    float* smf = (float*)smc;

    const int m  = blockIdx.z;
    const int n0 = blockIdx.x * 128;

    const int tid = threadIdx.x;
    const int wid = tid >> 5;
    const int lid = tid & 31;
    const int wy  = wid >> 2;
    const int wx  = wid & 3;

    const float* xm = x + (size_t)m * CC * NN;
    const uint32_t sbase = smem_u32(smc);

    const int ar = tid >> 2;
    const int as = tid & 3;
    const float* wrow = (ar < 32) ? wq + ar * CC : wk + (ar - 32) * CC;
    const int br = tid >> 3;
    const int bs = tid & 7;

    auto prefetch = [&](int c) {
        const int k0 = c * 32;
        const uint32_t st = sbase + (c & 1) * K1_STAGE;
        cp16(st + ar * 160 + as * 16, wrow + k0 + as * 4);
        cp16(st + ar * 160 + (as + 4) * 16, wrow + k0 + (as + 4) * 4);
        const uint32_t bb = st + K1_A_BYTES;
        #pragma unroll
        for (int j = 0; j < 4; j++)
            cp16(bb + br * 544 + (bs + j * 8) * 16,
                 xm + (size_t)(k0 + br) * NN + n0 + (bs + j * 8) * 4);
        CP_COMMIT();
    };

    wmma::fragment<wmma::accumulator, 16, 16, 8, float> acc[2][2];
    #pragma unroll
    for (int i = 0; i < 2; i++)
        #pragma unroll
        for (int j = 0; j < 2; j++) wmma::fill_fragment(acc[i][j], 0.0f);

    prefetch(0);
    for (int c = 0; c < 8; c++) {
        if (c < 7) { prefetch(c + 1); CP_WAIT(1); }
        else       { CP_WAIT(0); }
        __syncthreads();

        const float* As = (const float*)(smc + (c & 1) * K1_STAGE);
        const float* Bs = (const float*)(smc + (c & 1) * K1_STAGE + K1_A_BYTES);

        #pragma unroll
        for (int kk = 0; kk < 4; kk++) {
            wmma::fragment<wmma::matrix_a, 16, 16, 8, wmma::precision::tf32,
                           wmma::row_major> af[2];
            wmma::fragment<wmma::matrix_b, 16, 16, 8, wmma::precision::tf32,
                           wmma::row_major> bf[2];
            #pragma unroll
            for (int i = 0; i < 2; i++)
                wmma::load_matrix_sync(af[i],
                    &As[(wy * 32 + i * 16) * K1_A_LD + kk * 8], K1_A_LD);
            #pragma unroll
            for (int j = 0; j < 2; j++)
                wmma::load_matrix_sync(bf[j],
                    &Bs[kk * 8 * K1_B_LD + wx * 32 + j * 16], K1_B_LD);
            #pragma unroll
            for (int i = 0; i < 2; i++)
                #pragma unroll
                for (int j = 0; j < 2; j++)
                    wmma::mma_sync(acc[i][j], af[i], bf[j], acc[i][j]);
        }
        __syncthreads();
    }

    float* ws = smf + wid * (32 * K1_SCR_LD);
    #pragma unroll
    for (int i = 0; i < 2; i++)
        #pragma unroll
        for (int j = 0; j < 2; j++)
            wmma::store_matrix_sync(&ws[(i * 16) * K1_SCR_LD + j * 16],
                                    acc[i][j], K1_SCR_LD, wmma::mem_row_major);
    __syncwarp();

    #pragma unroll
    for (int it = 0; it < 8; it++) {
        int r  = it * 4 + (lid >> 3);
        int c4 = lid & 7;
        int gr = wy * 32 + r;
        float bb = (gr < 32) ? bq[gr] : bk[gr - 32];
        float4 a = *(const float4*)&ws[r * K1_SCR_LD + c4 * 4];
        a.x += bb; a.y += bb; a.z += bb; a.w += bb;
        *(float4*)&g_qkv[(size_t)(m * RR + gr) * NN + n0 + wx * 32 + c4 * 4] = a;
    }
}

// ---------------------------------------------------------------------------
// Kernel 1b: v projection via bf16 wmma (m0 chunk offset).
// ---------------------------------------------------------------------------
#define A_LD 40
#define B_LD 136
#define A_BYTES (128 * A_LD * 2)
#define B_BYTES (32 * B_LD * 2)
#define STAGE_BYTES (A_BYTES + B_BYTES)
#define SCR_LD 36
#define SMEM_K3 73728

__global__ __launch_bounds__(256) void k_qkv_v(
    const float* __restrict__ bv, int m0)
{
    extern __shared__ __align__(16) char smc[];
    float* smf = (float*)smc;

    const int m  = m0 + blockIdx.z;
    const int c0 = blockIdx.y * 128;
    const int j0 = blockIdx.x * 128;

    const int tid = threadIdx.x;
    const int wid = tid >> 5;
    const int lid = tid & 31;
    const int wy  = wid >> 2;
    const int wx  = wid & 3;

    const __nv_bfloat16* xb = g_xb + (size_t)m * CC * NN;
    const uint32_t sbase = smem_u32(smc);

    const int a_row0 = tid >> 1;
    const int a_seg0 = (tid & 1) * 2;
    const int b_row  = tid >> 4;
    const int b_seg  = tid & 15;

    auto prefetch = [&](int c) {
        const int k0 = c * 32;
        const uint32_t st = sbase + (c & 1) * STAGE_BYTES;
        cp16(st + a_row0 * 80 + a_seg0 * 16,
             g_wvb + (size_t)(c0 + a_row0) * CC + k0 + a_seg0 * 8);
        cp16(st + a_row0 * 80 + (a_seg0 + 1) * 16,
             g_wvb + (size_t)(c0 + a_row0) * CC + k0 + (a_seg0 + 1) * 8);
        const uint32_t bb = st + A_BYTES;
        cp16(bb + b_row * 272 + b_seg * 16,
             xb + (size_t)(k0 + b_row) * NN + j0 + b_seg * 8);
        cp16(bb + (b_row + 16) * 272 + b_seg * 16,
             xb + (size_t)(k0 + b_row + 16) * NN + j0 + b_seg * 8);
        CP_COMMIT();
    };

    wmma::fragment<wmma::accumulator, 16, 16, 16, float> acc[4][2];
    #pragma unroll
    for (int i = 0; i < 4; i++)
        #pragma unroll
        for (int j = 0; j < 2; j++) wmma::fill_fragment(acc[i][j], 0.0f);

    prefetch(0);
    for (int c = 0; c < 8; c++) {
        if (c < 7) { prefetch(c + 1); CP_WAIT(1); }
        else       { CP_WAIT(0); }
        __syncthreads();

        const __nv_bfloat16* As =
            (const __nv_bfloat16*)(smc + (c & 1) * STAGE_BYTES);
        const __nv_bfloat16* Bs =
            (const __nv_bfloat16*)(smc + (c & 1) * STAGE_BYTES + A_BYTES);

        #pragma unroll
        for (int kk = 0; kk < 2; kk++) {
            wmma::fragment<wmma::matrix_a, 16, 16, 16, __nv_bfloat16,
                           wmma::row_major> af[4];
            wmma::fragment<wmma::matrix_b, 16, 16, 16, __nv_bfloat16,
                           wmma::row_major> bf[2];
            #pragma unroll
            for (int i = 0; i < 4; i++)
                wmma::load_matrix_sync(af[i],
                    &As[(wy * 64 + i * 16) * A_LD + kk * 16], A_LD);
            #pragma unroll
            for (int j = 0; j < 2; j++)
                wmma::load_matrix_sync(bf[j],
                    &Bs[kk * 16 * B_LD + wx * 32 + j * 16], B_LD);
            #pragma unroll
            for (int i = 0; i < 4; i++)
                #pragma unroll
                for (int j = 0; j < 2; j++)
                    wmma::mma_sync(acc[i][j], af[i], bf[j], acc[i][j]);
        }
        __syncthreads();
    }

    float* ws = smf + wid * (64 * SCR_LD);
    #pragma unroll
    for (int i = 0; i < 4; i++)
        #pragma unroll
        for (int j = 0; j < 2; j++)
            wmma::store_matrix_sync(&ws[(i * 16) * SCR_LD + j * 16],
                                    acc[i][j], SCR_LD, wmma::mem_row_major);
    __syncwarp();

    const int rbase = c0 + wy * 64;
    const int cbase = j0 + wx * 32;
    #pragma unroll
    for (int it = 0; it < 16; it++) {
        int r  = it * 4 + (lid >> 3);
        int c4 = lid & 7;
        int gr = rbase + r;
        float bb = bv[gr];
        float4 a = *(const float4*)&ws[r * SCR_LD + c4 * 4];
        a.x += bb; a.y += bb; a.z += bb; a.w += bb;
        *(float4*)&g_qkv[(size_t)(m * RR + 64 + gr) * NN + cbase + c4 * 4] = a;
    }
}

// ---------------------------------------------------------------------------
// Kernel 2: energy + exp + rowsum via tf32 wmma (64-row blocks, 2/SM).
// ---------------------------------------------------------------------------
#define K2_Q_LD 68
#define K2_K_LD 136
#define K2_S_LD 132
#define K2_Q   0
#define K2_K   (32 * K2_Q_LD)
#define K2_SCR (K2_K + 2 * 32 * K2_K_LD)
#define K2_SUM (K2_SCR + 64 * K2_S_LD)
#define SMEM_K2 ((K2_SUM + 64) * 4)

__global__ __launch_bounds__(256, 2) void k_attn_wmma(int m0)
{
    extern __shared__ __align__(16) char smc[];
    float* smf = (float*)smc;
    float* Qs  = smf + K2_Q;
    float* scr = smf + K2_SCR;
    float* rsum = smf + K2_SUM;

    const int m  = m0 + blockIdx.y;
    const int n0 = blockIdx.x * 64;

    const int tid = threadIdx.x;
    const int wid = tid >> 5;
    const int wy  = wid >> 2;
    const int wx  = wid & 3;

    const float* qbase = g_qkv + (size_t)m * RR * NN;
    const float* kbase = qbase + 32 * NN;
    __nv_bfloat16* am = g_attn_bf + (size_t)m * NN * NN;

    const uint32_t sbase = smem_u32(smc);
    const uint32_t qb = sbase + K2_Q * 4;
    const uint32_t kb = sbase + K2_K * 4;

    if (tid < 64) rsum[tid] = 0.f;

    #pragma unroll
    for (int p = 0; p < 2; p++) {
        int idx = tid + p * 256;
        int o   = idx >> 4;
        int sg  = idx & 15;
        cp16(qb + o * 272 + sg * 16, qbase + (size_t)o * NN + n0 + sg * 4);
    }
    auto prefetch = [&](int s) {
        const uint32_t st = kb + (s & 1) * (32 * K2_K_LD * 4);
        const int j0 = s * 128;
        #pragma unroll
        for (int p = 0; p < 4; p++) {
            int idx = tid + p * 256;
            int o   = idx >> 5;
            int sg  = idx & 31;
            cp16(st + o * 544 + sg * 16, kbase + (size_t)o * NN + j0 + sg * 4);
        }
        CP_COMMIT();
    };
    prefetch(0);

    for (int s = 0; s < 8; s++) {
        if (s < 7) { prefetch(s + 1); CP_WAIT(1); }
        else       { CP_WAIT(0); }
        __syncthreads();

        const float* Ks = smf + K2_K + (s & 1) * (32 * K2_K_LD);

        wmma::fragment<wmma::accumulator, 16, 16, 8, float> acc[2][2];
        #pragma unroll
        for (int i = 0; i < 2; i++)
            #pragma unroll
            for (int j = 0; j < 2; j++) wmma::fill_fragment(acc[i][j], 0.0f);

        #pragma unroll
        for (int kk = 0; kk < 4; kk++) {
            wmma::fragment<wmma::matrix_a, 16, 16, 8, wmma::precision::tf32,
                           wmma::col_major> af[2];
            wmma::fragment<wmma::matrix_b, 16, 16, 8, wmma::precision::tf32,
                           wmma::row_major> bf[2];
            #pragma unroll
            for (int i = 0; i < 2; i++)
                wmma::load_matrix_sync(af[i],
                    &Qs[(kk * 8) * K2_Q_LD + wy * 32 + i * 16], K2_Q_LD);
            #pragma unroll
            for (int j = 0; j < 2; j++)
                wmma::load_matrix_sync(bf[j],
                    &Ks[(kk * 8) * K2_K_LD + wx * 32 + j * 16], K2_K_LD);
            #pragma unroll
            for (int i = 0; i < 2; i++)
                #pragma unroll
                for (int j = 0; j < 2; j++)
                    wmma::mma_sync(acc[i][j], af[i], bf[j], acc[i][j]);
        }

        #pragma unroll
        for (int i = 0; i < 2; i++)
            #pragma unroll
            for (int j = 0; j < 2; j++)
                #pragma unroll
                for (int e = 0; e < acc[i][j].num_elements; e++)
                    acc[i][j].x[e] = __expf(acc[i][j].x[e]);

        #pragma unroll
        for (int i = 0; i < 2; i++)
            #pragma unroll
            for (int j = 0; j < 2; j++)
                wmma::store_matrix_sync(
                    &scr[(wy * 32 + i * 16) * K2_S_LD + wx * 32 + j * 16],
                    acc[i][j], K2_S_LD, wmma::mem_row_major);
        __syncthreads();

        {
            const int r  = tid >> 2;
            const int q4 = tid & 3;
            const float* srow = &scr[r * K2_S_LD + q4 * 32];
            __nv_bfloat16* arow = am + (size_t)(n0 + r) * NN + s * 128 + q4 * 32;
            float ssum = 0.f;
            #pragma unroll
            for (int it = 0; it < 4; it++) {
                float4 e0 = *(const float4*)&srow[it * 8];
                float4 e1 = *(const float4*)&srow[it * 8 + 4];
                ssum += ((e0.x + e0.y) + (e0.z + e0.w))
                      + ((e1.x + e1.y) + (e1.z + e1.w));
                __nv_bfloat162 h0 = __floats2bfloat162_rn(e0.x, e0.y);
                __nv_bfloat162 h1 = __floats2bfloat162_rn(e0.z, e0.w);
                __nv_bfloat162 h2 = __floats2bfloat162_rn(e1.x, e1.y);
                __nv_bfloat162 h3 = __floats2bfloat162_rn(e1.z, e1.w);
                uint4 st4;
                st4.x = *(uint32_t*)&h0; st4.y = *(uint32_t*)&h1;
                st4.z = *(uint32_t*)&h2; st4.w = *(uint32_t*)&h3;
                *(uint4*)&arow[it * 8] = st4;
            }
            ssum += __shfl_xor_sync(0xffffffffu, ssum, 1);
            ssum += __shfl_xor_sync(0xffffffffu, ssum, 2);
            if (q4 == 0) rsum[r] += ssum;
        }
        __syncthreads();
    }

    if (tid < 64) rsum[tid] = 1.0f / rsum[tid];
    __syncthreads();

    const float* vm = g_qkv + (size_t)(m * RR + 64) * NN;
    __nv_bfloat16* vb = g_vb + (size_t)m * CC * NN;
    const int col4 = (tid & 15) * 4;
    const float4 izv = *(const float4*)&rsum[col4];
    #pragma unroll
    for (int p = 0; p < 16; p++) {
        int c = p * 16 + (tid >> 4);
        float4 v = *(const float4*)&vm[(size_t)c * NN + n0 + col4];
        v.x *= izv.x; v.y *= izv.y; v.z *= izv.z; v.w *= izv.w;
        __nv_bfloat162 h0 = __floats2bfloat162_rn(v.x, v.y);
        __nv_bfloat162 h1 = __floats2bfloat162_rn(v.z, v.w);
        uint2 st;
        st.x = *(uint32_t*)&h0; st.y = *(uint32_t*)&h1;
        *(uint2*)&vb[(size_t)c * NN + n0 + col4] = st;
    }
}

// ---------------------------------------------------------------------------
// Kernel 3: out = gamma * (V' @ exp(E)) + x  via bf16 wmma.
// Reg-capped to 128 (2 blocks/SM worth of RF) so an out block can co-reside
// with an attn block during the staggered overlap phase.
// ---------------------------------------------------------------------------
__global__ __launch_bounds__(256, 2) void k_out_wmma(
    const float* __restrict__ x, const float* __restrict__ gp,
    float* __restrict__ out, int m0)
{
    extern __shared__ __align__(16) char smc[];
    float* smf = (float*)smc;

    const int m  = m0 + blockIdx.z;
    const int c0 = blockIdx.y * 128;
    const int j0 = blockIdx.x * 128;

    const int tid = threadIdx.x;
    const int wid = tid >> 5;
    const int lid = tid & 31;
    const int wy  = wid >> 2;
    const int wx  = wid & 3;

    const __nv_bfloat16* vb = g_vb + (size_t)m * CC * NN;
    const __nv_bfloat16* am = g_attn_bf + (size_t)m * NN * NN;
    const uint32_t sbase = smem_u32(smc);

    const int a_row0 = tid >> 1;
    const int a_seg0 = (tid & 1) * 2;
    const int b_row  = tid >> 4;
    const int b_seg  = tid & 15;

    auto prefetch = [&](int c) {
        const int k0 = c * 32;
        const uint32_t st = sbase + (c & 1) * STAGE_BYTES;
        cp16(st + a_row0 * 80 + a_seg0 * 16,
             vb + (size_t)(c0 + a_row0) * NN + k0 + a_seg0 * 8);
        cp16(st + a_row0 * 80 + (a_seg0 + 1) * 16,
             vb + (size_t)(c0 + a_row0) * NN + k0 + (a_seg0 + 1) * 8);
        const uint32_t bb = st + A_BYTES;
        cp16(bb + b_row * 272 + b_seg * 16,
             am + (size_t)(k0 + b_row) * NN + j0 + b_seg * 8);
        cp16(bb + (b_row + 16) * 272 + b_seg * 16,
             am + (size_t)(k0 + b_row + 16) * NN + j0 + b_seg * 8);
        CP_COMMIT();
    };

    wmma::fragment<wmma::accumulator, 16, 16, 16, float> acc[4][2];
    #pragma unroll
    for (int i = 0; i < 4; i++)
        #pragma unroll
        for (int j = 0; j < 2; j++) wmma::fill_fragment(acc[i][j], 0.0f);

    prefetch(0);
    for (int c = 0; c < 32; c++) {
        if (c < 31) { prefetch(c + 1); CP_WAIT(1); }
        else        { CP_WAIT(0); }
        __syncthreads();

        const __nv_bfloat16* As =
            (const __nv_bfloat16*)(smc + (c & 1) * STAGE_BYTES);
        const __nv_bfloat16* Bs =
            (const __nv_bfloat16*)(smc + (c & 1) * STAGE_BYTES + A_BYTES);

        #pragma unroll
        for (int kk = 0; kk < 2; kk++) {
            wmma::fragment<wmma::matrix_a, 16, 16, 16, __nv_bfloat16,
                           wmma::row_major> af[4];
            wmma::fragment<wmma::matrix_b, 16, 16, 16, __nv_bfloat16,
                           wmma::row_major> bf[2];
            #pragma unroll
            for (int i = 0; i < 4; i++)
                wmma::load_matrix_sync(af[i],
                    &As[(wy * 64 + i * 16) * A_LD + kk * 16], A_LD);
            #pragma unroll
            for (int j = 0; j < 2; j++)
                wmma::load_matrix_sync(bf[j],
                    &Bs[kk * 16 * B_LD + wx * 32 + j * 16], B_LD);
            #pragma unroll
            for (int i = 0; i < 4; i++)
                #pragma unroll
                for (int j = 0; j < 2; j++)
                    wmma::mma_sync(acc[i][j], af[i], bf[j], acc[i][j]);
        }
        __syncthreads();
    }

    float* ws = smf + wid * (64 * SCR_LD);
    #pragma unroll
    for (int i = 0; i < 4; i++)
        #pragma unroll
        for (int j = 0; j < 2; j++)
            wmma::store_matrix_sync(&ws[(i * 16) * SCR_LD + j * 16],
                                    acc[i][j], SCR_LD, wmma::mem_row_major);
    __syncwarp();

    const float g = *gp;
    const int rbase = c0 + wy * 64;
    const int cbase = j0 + wx * 32;
    const float* xm = x + (size_t)m * CC * NN;
    float* om = out + (size_t)m * CC * NN;
    #pragma unroll
    for (int it = 0; it < 16; it++) {
        int r  = it * 4 + (lid >> 3);
        int c4 = lid & 7;
        float4 a  = *(const float4*)&ws[r * SCR_LD + c4 * 4];
        const float* xrow = xm + (size_t)(rbase + r) * NN + cbase;
        float4 xv = *(const float4*)&xrow[c4 * 4];
        float4 o;
        o.x = g * a.x + xv.x;
        o.y = g * a.y + xv.y;
        o.z = g * a.z + xv.z;
        o.w = g * a.w + xv.w;
        *(float4*)&om[(size_t)(rbase + r) * NN + cbase + c4 * 4] = o;
    }
}

// ---------------------------------------------------------------------------
// Launch: staggered fork-join so attn of one half co-runs with out of the
// other half (complementary pipes, co-resident blocks).
//   S0: cvt --(ecvt)      v(0)  [wait eqk]  attn(0) --(eA0)  out(0)
//   S1: qk --(eqk)  [wait ecvt]  v(1)  [wait eA0]  attn(1)  out(1) --(eend)
// ---------------------------------------------------------------------------
#define CH (MB / 2)   // 16 batches per half
extern "C" void kernel_launch(void* const* d_in, const int* in_sizes, int n_in,
                              void* d_out, int out_size)
{
    const float* x     = (const float*)d_in[0];
    const float* wq    = (const float*)d_in[1];
    const float* bq    = (const float*)d_in[2];
    const float* wk    = (const float*)d_in[3];
    const float* bk    = (const float*)d_in[4];
    const float* wv    = (const float*)d_in[5];
    const float* bv    = (const float*)d_in[6];
    const float* gamma = (const float*)d_in[7];
    float* out = (float*)d_out;

    cudaFuncSetAttribute(k_qkv_qk,
                         cudaFuncAttributeMaxDynamicSharedMemorySize, SMEM_K1);
    cudaFuncSetAttribute(k_qkv_v,
                         cudaFuncAttributeMaxDynamicSharedMemorySize, SMEM_K3);
    cudaFuncSetAttribute(k_attn_wmma,
                         cudaFuncAttributeMaxDynamicSharedMemorySize, SMEM_K2);
    cudaFuncSetAttribute(k_out_wmma,
                         cudaFuncAttributeMaxDynamicSharedMemorySize, SMEM_K3);

    // fork side stream off the (possibly capturing) default stream
    cudaEventRecord(g_e0, 0);
    cudaStreamWaitEvent(g_s2, g_e0, 0);

    // S1: q,k projection for ALL m (independent of cvt)
    dim3 g1a(NN / 128, 1, MB);
    k_qkv_qk<<<g1a, 256, SMEM_K1, g_s2>>>(x, wq, bq, wk, bk);
    cudaEventRecord(g_eqk, g_s2);

    // S0: bf16 conversion
    k_cvt<<<(XB4 + WV4 + 255) / 256, 256>>>(x, wv);
    cudaEventRecord(g_ecvt, 0);

    dim3 gv(NN / 128, CC / 128, CH);   // 256 blocks
    dim3 ga(NN / 64, CH);              // 256 blocks
    dim3 go(NN / 128, CC / 128, CH);   // 256 blocks

    // S0 chain: first half
    k_qkv_v<<<gv, 256, SMEM_K3>>>(bv, 0);
    cudaStreamWaitEvent(0, g_eqk, 0);
    k_attn_wmma<<<ga, 256, SMEM_K2>>>(0);
    cudaEventRecord(g_eA0, 0);
    k_out_wmma<<<go, 256, SMEM_K3>>>(x, gamma, out, 0);

    // S1 chain: second half (attn staggered after S0's attn)
    cudaStreamWaitEvent(g_s2, g_ecvt, 0);
    k_qkv_v<<<gv, 256, SMEM_K3, g_s2>>>(bv, CH);
    cudaStreamWaitEvent(g_s2, g_eA0, 0);
    k_attn_wmma<<<ga, 256, SMEM_K2, g_s2>>>(CH);
    k_out_wmma<<<go, 256, SMEM_K3, g_s2>>>(x, gamma, out, CH);
    cudaEventRecord(g_eend, g_s2);

    // join
    cudaStreamWaitEvent(0, g_eend, 0);
}

// round 17
// speedup vs baseline: 1.1794x; 1.1794x over previous
#include <cuda_runtime.h>
#include <cstdint>
#include <mma.h>
#include <cuda_bf16.h>

using namespace nvcuda;

// Problem constants (fixed shapes)
#define MB 32      // effective batch m = B*T (raw-reinterpret reshape)
#define CC 256     // channels
#define NN 1024    // pixels per map (32*32)
#define RR 320     // fused qkv rows: 32 q + 32 k + 256 v

typedef unsigned long long u64;

// Scratch (module-load allocated; no cudaMalloc anywhere)
__device__ float g_qkv[MB * RR * NN];                         // 40 MB fp32 q,k,v
__device__ __nv_bfloat16 g_attn_bf[(size_t)MB * NN * NN];     // 67 MB exp(E) bf16
__device__ __nv_bfloat16 g_vb[(size_t)MB * CC * NN];          // 17 MB V*(1/Z) bf16
__device__ __nv_bfloat16 g_xb[(size_t)MB * CC * NN];          // 17 MB x in bf16
__device__ __nv_bfloat16 g_wvb[CC * CC];                      // wv in bf16

// ---- orchestration objects (static-init; no device-memory allocation) ------
static cudaStream_t g_s2;
static cudaEvent_t g_e0, g_eqk, g_ecvt, g_eend;
namespace {
struct OrchInit {
    OrchInit() {
        cudaStreamCreateWithFlags(&g_s2, cudaStreamNonBlocking);
        cudaEventCreateWithFlags(&g_e0,   cudaEventDisableTiming);
        cudaEventCreateWithFlags(&g_eqk,  cudaEventDisableTiming);
        cudaEventCreateWithFlags(&g_ecvt, cudaEventDisableTiming);
        cudaEventCreateWithFlags(&g_eend, cudaEventDisableTiming);
    }
};
static OrchInit g_orch_init;
}

// ---- cp.async helpers (arch-neutral, sm_80+) --------------------------------
__device__ __forceinline__ uint32_t smem_u32(const void* p) {
    uint32_t a;
    asm("{ .reg .u64 t; cvta.to.shared.u64 t, %1; cvt.u32.u64 %0, t; }"
        : "=r"(a) : "l"(p));
    return a;
}
__device__ __forceinline__ void cp16(uint32_t dst, const void* src) {
    asm volatile("cp.async.cg.shared.global [%0], [%1], 16;"
                 :: "r"(dst), "l"(src));
}
#define CP_COMMIT() asm volatile("cp.async.commit_group;" ::: "memory")
#define CP_WAIT(n)  asm volatile("cp.async.wait_group %0;" :: "n"(n) : "memory")

// ---------------------------------------------------------------------------
// Kernel 0: convert x and wv to bf16 (one-time, ~50MB traffic)
// ---------------------------------------------------------------------------
#define XB4 (MB * CC * NN / 4)
#define WV4 (CC * CC / 4)
__global__ __launch_bounds__(256) void k_cvt(
    const float* __restrict__ x, const float* __restrict__ wv)
{
    int idx = blockIdx.x * 256 + threadIdx.x;
    if (idx < XB4) {
        float4 v = ((const float4*)x)[idx];
        __nv_bfloat162 h0 = __floats2bfloat162_rn(v.x, v.y);
        __nv_bfloat162 h1 = __floats2bfloat162_rn(v.z, v.w);
        uint2 st;
        st.x = *(uint32_t*)&h0; st.y = *(uint32_t*)&h1;
        ((uint2*)g_xb)[idx] = st;
    } else if (idx < XB4 + WV4) {
        int k = idx - XB4;
        float4 v = ((const float4*)wv)[k];
        __nv_bfloat162 h0 = __floats2bfloat162_rn(v.x, v.y);
        __nv_bfloat162 h1 = __floats2bfloat162_rn(v.z, v.w);
        uint2 st;
        st.x = *(uint32_t*)&h0; st.y = *(uint32_t*)&h1;
        ((uint2*)g_wvb)[k] = st;
    }
}

// ---------------------------------------------------------------------------
// Kernel 1a: q,k projection via tf32 wmma (64 rows only).
// ---------------------------------------------------------------------------
#define K1_A_LD 40
#define K1_B_LD 136
#define K1_A_BYTES (64 * K1_A_LD * 4)
#define K1_B_BYTES (32 * K1_B_LD * 4)
#define K1_STAGE (K1_A_BYTES + K1_B_BYTES)
#define K1_SCR_LD 36
#define SMEM_K1 (2 * K1_STAGE)

__global__ __launch_bounds__(256) void k_qkv_qk(
    const float* __restrict__ x,
    const float* __restrict__ wq, const float* __restrict__ bq,
    const float* __restrict__ wk, const float* __restrict__ bk)
{
    extern __shared__ __align__(16) char smc[];
    float* smf = (float*)smc;

    const int m  = blockIdx.z;
    const int n0 = blockIdx.x * 128;

    const int tid = threadIdx.x;
    const int wid = tid >> 5;
    const int lid = tid & 31;
    const int wy  = wid >> 2;
    const int wx  = wid & 3;

    const float* xm = x + (size_t)m * CC * NN;
    const uint32_t sbase = smem_u32(smc);

    const int ar = tid >> 2;
    const int as = tid & 3;
    const float* wrow = (ar < 32) ? wq + ar * CC : wk + (ar - 32) * CC;
    const int br = tid >> 3;
    const int bs = tid & 7;

    auto prefetch = [&](int c) {
        const int k0 = c * 32;
        const uint32_t st = sbase + (c & 1) * K1_STAGE;
        cp16(st + ar * 160 + as * 16, wrow + k0 + as * 4);
        cp16(st + ar * 160 + (as + 4) * 16, wrow + k0 + (as + 4) * 4);
        const uint32_t bb = st + K1_A_BYTES;
        #pragma unroll
        for (int j = 0; j < 4; j++)
            cp16(bb + br * 544 + (bs + j * 8) * 16,
                 xm + (size_t)(k0 + br) * NN + n0 + (bs + j * 8) * 4);
        CP_COMMIT();
    };

    wmma::fragment<wmma::accumulator, 16, 16, 8, float> acc[2][2];
    #pragma unroll
    for (int i = 0; i < 2; i++)
        #pragma unroll
        for (int j = 0; j < 2; j++) wmma::fill_fragment(acc[i][j], 0.0f);

    prefetch(0);
    for (int c = 0; c < 8; c++) {
        if (c < 7) { prefetch(c + 1); CP_WAIT(1); }
        else       { CP_WAIT(0); }
        __syncthreads();

        const float* As = (const float*)(smc + (c & 1) * K1_STAGE);
        const float* Bs = (const float*)(smc + (c & 1) * K1_STAGE + K1_A_BYTES);

        #pragma unroll
        for (int kk = 0; kk < 4; kk++) {
            wmma::fragment<wmma::matrix_a, 16, 16, 8, wmma::precision::tf32,
                           wmma::row_major> af[2];
            wmma::fragment<wmma::matrix_b, 16, 16, 8, wmma::precision::tf32,
                           wmma::row_major> bf[2];
            #pragma unroll
            for (int i = 0; i < 2; i++)
                wmma::load_matrix_sync(af[i],
                    &As[(wy * 32 + i * 16) * K1_A_LD + kk * 8], K1_A_LD);
            #pragma unroll
            for (int j = 0; j < 2; j++)
                wmma::load_matrix_sync(bf[j],
                    &Bs[kk * 8 * K1_B_LD + wx * 32 + j * 16], K1_B_LD);
            #pragma unroll
            for (int i = 0; i < 2; i++)
                #pragma unroll
                for (int j = 0; j < 2; j++)
                    wmma::mma_sync(acc[i][j], af[i], bf[j], acc[i][j]);
        }
        __syncthreads();
    }

    float* ws = smf + wid * (32 * K1_SCR_LD);
    #pragma unroll
    for (int i = 0; i < 2; i++)
        #pragma unroll
        for (int j = 0; j < 2; j++)
            wmma::store_matrix_sync(&ws[(i * 16) * K1_SCR_LD + j * 16],
                                    acc[i][j], K1_SCR_LD, wmma::mem_row_major);
    __syncwarp();

    #pragma unroll
    for (int it = 0; it < 8; it++) {
        int r  = it * 4 + (lid >> 3);
        int c4 = lid & 7;
        int gr = wy * 32 + r;
        float bb = (gr < 32) ? bq[gr] : bk[gr - 32];
        float4 a = *(const float4*)&ws[r * K1_SCR_LD + c4 * 4];
        a.x += bb; a.y += bb; a.z += bb; a.w += bb;
        *(float4*)&g_qkv[(size_t)(m * RR + gr) * NN + n0 + wx * 32 + c4 * 4] = a;
    }
}

// ---------------------------------------------------------------------------
// Kernel 1b: v projection via bf16 wmma (m0 chunk offset).
// ---------------------------------------------------------------------------
#define A_LD 40
#define B_LD 136
#define A_BYTES (128 * A_LD * 2)
#define B_BYTES (32 * B_LD * 2)
#define STAGE_BYTES (A_BYTES + B_BYTES)
#define SCR_LD 36
#define SMEM_K3 73728

__global__ __launch_bounds__(256) void k_qkv_v(
    const float* __restrict__ bv, int m0)
{
    extern __shared__ __align__(16) char smc[];
    float* smf = (float*)smc;

    const int m  = m0 + blockIdx.z;
    const int c0 = blockIdx.y * 128;
    const int j0 = blockIdx.x * 128;

    const int tid = threadIdx.x;
    const int wid = tid >> 5;
    const int lid = tid & 31;
    const int wy  = wid >> 2;
    const int wx  = wid & 3;

    const __nv_bfloat16* xb = g_xb + (size_t)m * CC * NN;
    const uint32_t sbase = smem_u32(smc);

    const int a_row0 = tid >> 1;
    const int a_seg0 = (tid & 1) * 2;
    const int b_row  = tid >> 4;
    const int b_seg  = tid & 15;

    auto prefetch = [&](int c) {
        const int k0 = c * 32;
        const uint32_t st = sbase + (c & 1) * STAGE_BYTES;
        cp16(st + a_row0 * 80 + a_seg0 * 16,
             g_wvb + (size_t)(c0 + a_row0) * CC + k0 + a_seg0 * 8);
        cp16(st + a_row0 * 80 + (a_seg0 + 1) * 16,
             g_wvb + (size_t)(c0 + a_row0) * CC + k0 + (a_seg0 + 1) * 8);
        const uint32_t bb = st + A_BYTES;
        cp16(bb + b_row * 272 + b_seg * 16,
             xb + (size_t)(k0 + b_row) * NN + j0 + b_seg * 8);
        cp16(bb + (b_row + 16) * 272 + b_seg * 16,
             xb + (size_t)(k0 + b_row + 16) * NN + j0 + b_seg * 8);
        CP_COMMIT();
    };

    wmma::fragment<wmma::accumulator, 16, 16, 16, float> acc[4][2];
    #pragma unroll
    for (int i = 0; i < 4; i++)
        #pragma unroll
        for (int j = 0; j < 2; j++) wmma::fill_fragment(acc[i][j], 0.0f);

    prefetch(0);
    for (int c = 0; c < 8; c++) {
        if (c < 7) { prefetch(c + 1); CP_WAIT(1); }
        else       { CP_WAIT(0); }
        __syncthreads();

        const __nv_bfloat16* As =
            (const __nv_bfloat16*)(smc + (c & 1) * STAGE_BYTES);
        const __nv_bfloat16* Bs =
            (const __nv_bfloat16*)(smc + (c & 1) * STAGE_BYTES + A_BYTES);

        #pragma unroll
        for (int kk = 0; kk < 2; kk++) {
            wmma::fragment<wmma::matrix_a, 16, 16, 16, __nv_bfloat16,
                           wmma::row_major> af[4];
            wmma::fragment<wmma::matrix_b, 16, 16, 16, __nv_bfloat16,
                           wmma::row_major> bf[2];
            #pragma unroll
            for (int i = 0; i < 4; i++)
                wmma::load_matrix_sync(af[i],
                    &As[(wy * 64 + i * 16) * A_LD + kk * 16], A_LD);
            #pragma unroll
            for (int j = 0; j < 2; j++)
                wmma::load_matrix_sync(bf[j],
                    &Bs[kk * 16 * B_LD + wx * 32 + j * 16], B_LD);
            #pragma unroll
            for (int i = 0; i < 4; i++)
                #pragma unroll
                for (int j = 0; j < 2; j++)
                    wmma::mma_sync(acc[i][j], af[i], bf[j], acc[i][j]);
        }
        __syncthreads();
    }

    float* ws = smf + wid * (64 * SCR_LD);
    #pragma unroll
    for (int i = 0; i < 4; i++)
        #pragma unroll
        for (int j = 0; j < 2; j++)
            wmma::store_matrix_sync(&ws[(i * 16) * SCR_LD + j * 16],
                                    acc[i][j], SCR_LD, wmma::mem_row_major);
    __syncwarp();

    const int rbase = c0 + wy * 64;
    const int cbase = j0 + wx * 32;
    #pragma unroll
    for (int it = 0; it < 16; it++) {
        int r  = it * 4 + (lid >> 3);
        int c4 = lid & 7;
        int gr = rbase + r;
        float bb = bv[gr];
        float4 a = *(const float4*)&ws[r * SCR_LD + c4 * 4];
        a.x += bb; a.y += bb; a.z += bb; a.w += bb;
        *(float4*)&g_qkv[(size_t)(m * RR + 64 + gr) * NN + cbase + c4 * 4] = a;
    }
}

// ---------------------------------------------------------------------------
// Kernel 2: energy + exp + rowsum via tf32 wmma, 64-row blocks, 2/SM.
// Warp-private scratch + per-warp partial rowsums -> ONE barrier/slab.
// (R15 fixed: full 32-column emit per lane, uint4 st4[4].)
// ---------------------------------------------------------------------------
#define K2_Q_LD 68
#define K2_K_LD 136
#define K2_W_LD 36                                  // warp scr stride
#define K2_Q   0
#define K2_K   (32 * K2_Q_LD)                       // 2176
#define K2_SCR (K2_K + 2 * 32 * K2_K_LD)            // 10880
#define K2_SUM (K2_SCR + 8 * 32 * K2_W_LD)          // 20096  (8 warps x 32x36)
#define SMEM_K2 ((K2_SUM + 256) * 4)                // + rsum_p[4][64]

__global__ __launch_bounds__(256, 2) void k_attn_wmma(int m0)
{
    extern __shared__ __align__(16) char smc[];
    float* smf = (float*)smc;
    float* Qs  = smf + K2_Q;
    float* rsum_p = smf + K2_SUM;    // [4][64]

    const int m  = m0 + blockIdx.y;
    const int n0 = blockIdx.x * 64;

    const int tid = threadIdx.x;
    const int wid = tid >> 5;
    const int lid = tid & 31;
    const int wy  = wid >> 2;        // 0..1 (32 rows each)
    const int wx  = wid & 3;         // 0..3 (32 cols each)

    const float* qbase = g_qkv + (size_t)m * RR * NN;
    const float* kbase = qbase + 32 * NN;
    __nv_bfloat16* am = g_attn_bf + (size_t)m * NN * NN;

    const uint32_t sbase = smem_u32(smc);
    const uint32_t qb = sbase + K2_Q * 4;
    const uint32_t kb = sbase + K2_K * 4;

    rsum_p[tid] = 0.f;   // all 4x64 partials (256 threads)

    #pragma unroll
    for (int p = 0; p < 2; p++) {
        int idx = tid + p * 256;
        int o   = idx >> 4;
        int sg  = idx & 15;
        cp16(qb + o * 272 + sg * 16, qbase + (size_t)o * NN + n0 + sg * 4);
    }
    auto prefetch = [&](int s) {
        const uint32_t st = kb + (s & 1) * (32 * K2_K_LD * 4);
        const int j0 = s * 128;
        #pragma unroll
        for (int p = 0; p < 4; p++) {
            int idx = tid + p * 256;
            int o   = idx >> 5;
            int sg  = idx & 31;
            cp16(st + o * 544 + sg * 16, kbase + (size_t)o * NN + j0 + sg * 4);
        }
        CP_COMMIT();
    };
    prefetch(0);

    // per-warp private scratch: 32 rows x 36 floats
    float* ws = smf + K2_SCR + wid * (32 * K2_W_LD);
    // this warp's private partial-sum slot: rsum_p[wx][wy*32 + lid]
    float* myp = &rsum_p[wx * 64 + wy * 32 + lid];

    for (int s = 0; s < 8; s++) {
        if (s < 7) { prefetch(s + 1); CP_WAIT(1); }
        else       { CP_WAIT(0); }
        __syncthreads();   // ONE barrier per slab (stage reuse + Q ready)

        const float* Ks = smf + K2_K + (s & 1) * (32 * K2_K_LD);

        wmma::fragment<wmma::accumulator, 16, 16, 8, float> acc[2][2];
        #pragma unroll
        for (int i = 0; i < 2; i++)
            #pragma unroll
            for (int j = 0; j < 2; j++) wmma::fill_fragment(acc[i][j], 0.0f);

        #pragma unroll
        for (int kk = 0; kk < 4; kk++) {
            wmma::fragment<wmma::matrix_a, 16, 16, 8, wmma::precision::tf32,
                           wmma::col_major> af[2];
            wmma::fragment<wmma::matrix_b, 16, 16, 8, wmma::precision::tf32,
                           wmma::row_major> bf[2];
            #pragma unroll
            for (int i = 0; i < 2; i++)
                wmma::load_matrix_sync(af[i],
                    &Qs[(kk * 8) * K2_Q_LD + wy * 32 + i * 16], K2_Q_LD);
            #pragma unroll
            for (int j = 0; j < 2; j++)
                wmma::load_matrix_sync(bf[j],
                    &Ks[(kk * 8) * K2_K_LD + wx * 32 + j * 16], K2_K_LD);
            #pragma unroll
            for (int i = 0; i < 2; i++)
                #pragma unroll
                for (int j = 0; j < 2; j++)
                    wmma::mma_sync(acc[i][j], af[i], bf[j], acc[i][j]);
        }

        // exp in registers (elementwise on accumulator: layout-agnostic)
        #pragma unroll
        for (int i = 0; i < 2; i++)
            #pragma unroll
            for (int j = 0; j < 2; j++)
                #pragma unroll
                for (int e = 0; e < acc[i][j].num_elements; e++)
                    acc[i][j].x[e] = __expf(acc[i][j].x[e]);

        // store frags to WARP-PRIVATE scr (local coords 32x32, stride 36)
        #pragma unroll
        for (int i = 0; i < 2; i++)
            #pragma unroll
            for (int j = 0; j < 2; j++)
                wmma::store_matrix_sync(&ws[(i * 16) * K2_W_LD + j * 16],
                                        acc[i][j], K2_W_LD,
                                        wmma::mem_row_major);
        __syncwarp();

        // lane = local row; sum 32 cols, cvt, store 64B to gmem; add partial
        {
            float ssum = 0.f;
            uint4 st4[4];
            uint32_t* stw = (uint32_t*)st4;
            #pragma unroll
            for (int it = 0; it < 4; it++) {
                float4 e0 = *(const float4*)&ws[lid * K2_W_LD + it * 8];
                float4 e1 = *(const float4*)&ws[lid * K2_W_LD + it * 8 + 4];
                ssum += ((e0.x + e0.y) + (e0.z + e0.w))
                      + ((e1.x + e1.y) + (e1.z + e1.w));
                __nv_bfloat162 h0 = __floats2bfloat162_rn(e0.x, e0.y);
                __nv_bfloat162 h1 = __floats2bfloat162_rn(e0.z, e0.w);
                __nv_bfloat162 h2 = __floats2bfloat162_rn(e1.x, e1.y);
                __nv_bfloat162 h3 = __floats2bfloat162_rn(e1.z, e1.w);
                stw[it * 4 + 0] = *(uint32_t*)&h0;
                stw[it * 4 + 1] = *(uint32_t*)&h1;
                stw[it * 4 + 2] = *(uint32_t*)&h2;
                stw[it * 4 + 3] = *(uint32_t*)&h3;
            }
            __nv_bfloat16* arow =
                am + (size_t)(n0 + wy * 32 + lid) * NN + s * 128 + wx * 32;
            *(uint4*)&arow[0]  = st4[0];
            *(uint4*)&arow[8]  = st4[1];
            *(uint4*)&arow[16] = st4[2];
            *(uint4*)&arow[24] = st4[3];
            *myp += ssum;
        }
        __syncwarp();   // scr reuse next slab (warp-local)
    }

    __syncthreads();
    if (tid < 64) {
        float z = rsum_p[tid] + rsum_p[64 + tid]
                + rsum_p[128 + tid] + rsum_p[192 + tid];
        rsum_p[tid] = 1.0f / z;
    }
    __syncthreads();

    // V'[c][n0+col] = bf16( V[c][n0+col] * iz[col] ), 256 rows x 64 cols
    const float* vm = g_qkv + (size_t)(m * RR + 64) * NN;
    __nv_bfloat16* vb = g_vb + (size_t)m * CC * NN;
    const int col4 = (tid & 15) * 4;
    const float4 izv = *(const float4*)&rsum_p[col4];
    #pragma unroll
    for (int p = 0; p < 16; p++) {
        int c = p * 16 + (tid >> 4);
        float4 v = *(const float4*)&vm[(size_t)c * NN + n0 + col4];
        v.x *= izv.x; v.y *= izv.y; v.z *= izv.z; v.w *= izv.w;
        __nv_bfloat162 h0 = __floats2bfloat162_rn(v.x, v.y);
        __nv_bfloat162 h1 = __floats2bfloat162_rn(v.z, v.w);
        uint2 st;
        st.x = *(uint32_t*)&h0; st.y = *(uint32_t*)&h1;
        *(uint2*)&vb[(size_t)c * NN + n0 + col4] = st;
    }
}

// ---------------------------------------------------------------------------
// Kernel 3: out = gamma * (V' @ exp(E)) + x  via bf16 wmma. (R13 exact)
// ---------------------------------------------------------------------------
__global__ __launch_bounds__(256) void k_out_wmma(
    const float* __restrict__ x, const float* __restrict__ gp,
    float* __restrict__ out, int m0)
{
    extern __shared__ __align__(16) char smc[];
    float* smf = (float*)smc;

    const int m  = m0 + blockIdx.z;
    const int c0 = blockIdx.y * 128;
    const int j0 = blockIdx.x * 128;

    const int tid = threadIdx.x;
    const int wid = tid >> 5;
    const int lid = tid & 31;
    const int wy  = wid >> 2;
    const int wx  = wid & 3;

    const __nv_bfloat16* vb = g_vb + (size_t)m * CC * NN;
    const __nv_bfloat16* am = g_attn_bf + (size_t)m * NN * NN;
    const uint32_t sbase = smem_u32(smc);

    const int a_row0 = tid >> 1;
    const int a_seg0 = (tid & 1) * 2;
    const int b_row  = tid >> 4;
    const int b_seg  = tid & 15;

    auto prefetch = [&](int c) {
        const int k0 = c * 32;
        const uint32_t st = sbase + (c & 1) * STAGE_BYTES;
        cp16(st + a_row0 * 80 + a_seg0 * 16,
             vb + (size_t)(c0 + a_row0) * NN + k0 + a_seg0 * 8);
        cp16(st + a_row0 * 80 + (a_seg0 + 1) * 16,
             vb + (size_t)(c0 + a_row0) * NN + k0 + (a_seg0 + 1) * 8);
        const uint32_t bb = st + A_BYTES;
        cp16(bb + b_row * 272 + b_seg * 16,
             am + (size_t)(k0 + b_row) * NN + j0 + b_seg * 8);
        cp16(bb + (b_row + 16) * 272 + b_seg * 16,
             am + (size_t)(k0 + b_row + 16) * NN + j0 + b_seg * 8);
        CP_COMMIT();
    };

    wmma::fragment<wmma::accumulator, 16, 16, 16, float> acc[4][2];
    #pragma unroll
    for (int i = 0; i < 4; i++)
        #pragma unroll
        for (int j = 0; j < 2; j++) wmma::fill_fragment(acc[i][j], 0.0f);

    prefetch(0);
    for (int c = 0; c < 32; c++) {
        if (c < 31) { prefetch(c + 1); CP_WAIT(1); }
        else        { CP_WAIT(0); }
        __syncthreads();

        const __nv_bfloat16* As =
            (const __nv_bfloat16*)(smc + (c & 1) * STAGE_BYTES);
        const __nv_bfloat16* Bs =
            (const __nv_bfloat16*)(smc + (c & 1) * STAGE_BYTES + A_BYTES);

        #pragma unroll
        for (int kk = 0; kk < 2; kk++) {
            wmma::fragment<wmma::matrix_a, 16, 16, 16, __nv_bfloat16,
                           wmma::row_major> af[4];
            wmma::fragment<wmma::matrix_b, 16, 16, 16, __nv_bfloat16,
                           wmma::row_major> bf[2];
            #pragma unroll
            for (int i = 0; i < 4; i++)
                wmma::load_matrix_sync(af[i],
                    &As[(wy * 64 + i * 16) * A_LD + kk * 16], A_LD);
            #pragma unroll
            for (int j = 0; j < 2; j++)
                wmma::load_matrix_sync(bf[j],
                    &Bs[kk * 16 * B_LD + wx * 32 + j * 16], B_LD);
            #pragma unroll
            for (int i = 0; i < 4; i++)
                #pragma unroll
                for (int j = 0; j < 2; j++)
                    wmma::mma_sync(acc[i][j], af[i], bf[j], acc[i][j]);
        }
        __syncthreads();
    }

    float* ws = smf + wid * (64 * SCR_LD);
    #pragma unroll
    for (int i = 0; i < 4; i++)
        #pragma unroll
        for (int j = 0; j < 2; j++)
            wmma::store_matrix_sync(&ws[(i * 16) * SCR_LD + j * 16],
                                    acc[i][j], SCR_LD, wmma::mem_row_major);
    __syncwarp();

    const float g = *gp;
    const int rbase = c0 + wy * 64;
    const int cbase = j0 + wx * 32;
    const float* xm = x + (size_t)m * CC * NN;
    float* om = out + (size_t)m * CC * NN;
    #pragma unroll
    for (int it = 0; it < 16; it++) {
        int r  = it * 4 + (lid >> 3);
        int c4 = lid & 7;
        float4 a  = *(const float4*)&ws[r * SCR_LD + c4 * 4];
        const float* xrow = xm + (size_t)(rbase + r) * NN + cbase;
        float4 xv = *(const float4*)&xrow[c4 * 4];
        float4 o;
        o.x = g * a.x + xv.x;
        o.y = g * a.y + xv.y;
        o.z = g * a.z + xv.z;
        o.w = g * a.w + xv.w;
        *(float4*)&om[(size_t)(rbase + r) * NN + cbase + c4 * 4] = o;
    }
}

// ---------------------------------------------------------------------------
// Launch: R13 schedule (the 204.9us champion orchestration).
//   S0: cvt --(ecvt)        v(0..15)  [wait eqk]  attn(0..15)  out(0..15)
//   S1: qk --(eqk)  [wait ecvt]  v(16..31)  attn(16..31)  out(16..31) --(eend)
// ---------------------------------------------------------------------------
#define CH (MB / 2)   // 16 batches per half
extern "C" void kernel_launch(void* const* d_in, const int* in_sizes, int n_in,
                              void* d_out, int out_size)
{
    const float* x     = (const float*)d_in[0];
    const float* wq    = (const float*)d_in[1];
    const float* bq    = (const float*)d_in[2];
    const float* wk    = (const float*)d_in[3];
    const float* bk    = (const float*)d_in[4];
    const float* wv    = (const float*)d_in[5];
    const float* bv    = (const float*)d_in[6];
    const float* gamma = (const float*)d_in[7];
    float* out = (float*)d_out;

    cudaFuncSetAttribute(k_qkv_qk,
                         cudaFuncAttributeMaxDynamicSharedMemorySize, SMEM_K1);
    cudaFuncSetAttribute(k_qkv_v,
                         cudaFuncAttributeMaxDynamicSharedMemorySize, SMEM_K3);
    cudaFuncSetAttribute(k_attn_wmma,
                         cudaFuncAttributeMaxDynamicSharedMemorySize, SMEM_K2);
    cudaFuncSetAttribute(k_out_wmma,
                         cudaFuncAttributeMaxDynamicSharedMemorySize, SMEM_K3);

    // fork side stream off the (possibly capturing) default stream
    cudaEventRecord(g_e0, 0);
    cudaStreamWaitEvent(g_s2, g_e0, 0);

    // S1: q,k projection for ALL m (independent of cvt)
    dim3 g1a(NN / 128, 1, MB);
    k_qkv_qk<<<g1a, 256, SMEM_K1, g_s2>>>(x, wq, bq, wk, bk);
    cudaEventRecord(g_eqk, g_s2);

    // S0: bf16 conversion
    k_cvt<<<(XB4 + WV4 + 255) / 256, 256>>>(x, wv);
    cudaEventRecord(g_ecvt, 0);

    dim3 gv(NN / 128, CC / 128, CH);   // 256 blocks
    dim3 ga(NN / 64, CH);              // 256 blocks
    dim3 go(NN / 128, CC / 128, CH);   // 256 blocks

    // S0 chain: first m-half
    k_qkv_v<<<gv, 256, SMEM_K3>>>(bv, 0);
    cudaStreamWaitEvent(0, g_eqk, 0);
    k_attn_wmma<<<ga, 256, SMEM_K2>>>(0);
    k_out_wmma<<<go, 256, SMEM_K3>>>(x, gamma, out, 0);

    // S1 chain: second m-half
    cudaStreamWaitEvent(g_s2, g_ecvt, 0);
    k_qkv_v<<<gv, 256, SMEM_K3, g_s2>>>(bv, CH);
    k_attn_wmma<<<ga, 256, SMEM_K2, g_s2>>>(CH);
    k_out_wmma<<<go, 256, SMEM_K3, g_s2>>>(x, gamma, out, CH);
    cudaEventRecord(g_eend, g_s2);

    // join
    cudaStreamWaitEvent(0, g_eend, 0);
}